// round 3
// baseline (speedup 1.0000x reference)
#include <cuda_runtime.h>
#include <cstdint>

// Problem dims (fixed by the dataset)
#define BB 32
#define NN 4096          // 64*64
#define CC 256

// 8 MB scratch for aTa / attn (in-place softmax). __device__ global: allowed.
__device__ float g_aTa[(size_t)BB * CC * CC];

// ---------------------------------------------------------------------------
// Kernel 1: aTa[b,c,d] = sum_n x[b,n,c] * x[b,n,d]
// grid (CC/64, CC/64, BB), 256 threads, 64x64 tile, 4x4 micro-tile, K-chunk 32
// ---------------------------------------------------------------------------
__global__ void k_aTa(const float* __restrict__ x, const float* __restrict__ gamma) {
    if (gamma[0] == 0.0f) return;   // gamma==0 => gamma*aaTa == 0, skip all work

    const int b  = blockIdx.z;
    const int c0 = blockIdx.y * 64;
    const int d0 = blockIdx.x * 64;

    __shared__ float As[32][68];    // [n-chunk][c]   (+4 pad vs bank conflicts)
    __shared__ float Bs[32][68];    // [n-chunk][d]

    const float* xb = x + (size_t)b * NN * CC;

    float acc[4][4] = {};
    const int tc = threadIdx.x & 15;   // 16 col-groups of 4
    const int tr = threadIdx.x >> 4;   // 16 row-groups of 4

    for (int n0 = 0; n0 < NN; n0 += 32) {
        for (int i = threadIdx.x; i < 32 * 64; i += 256) {
            const int nn = i >> 6, cc = i & 63;
            const size_t base = (size_t)(n0 + nn) * CC;
            As[nn][cc] = xb[base + c0 + cc];
            Bs[nn][cc] = xb[base + d0 + cc];
        }
        __syncthreads();
        #pragma unroll
        for (int kk = 0; kk < 32; kk++) {
            float a[4], bb[4];
            #pragma unroll
            for (int i = 0; i < 4; i++) a[i]  = As[kk][tr * 4 + i];
            #pragma unroll
            for (int j = 0; j < 4; j++) bb[j] = Bs[kk][tc * 4 + j];
            #pragma unroll
            for (int i = 0; i < 4; i++)
                #pragma unroll
                for (int j = 0; j < 4; j++)
                    acc[i][j] = fmaf(a[i], bb[j], acc[i][j]);
        }
        __syncthreads();
    }

    float* outp = g_aTa + (size_t)b * CC * CC;
    #pragma unroll
    for (int i = 0; i < 4; i++)
        #pragma unroll
        for (int j = 0; j < 4; j++)
            outp[(size_t)(c0 + tr * 4 + i) * CC + d0 + tc * 4 + j] = acc[i][j];
}

// ---------------------------------------------------------------------------
// Kernel 2: row-wise stable softmax over last axis of aTa, in place.
// Persistent grid: 448 blocks loop over all BB*CC rows (cheap early-exit).
// ---------------------------------------------------------------------------
__global__ void k_softmax(const float* __restrict__ gamma) {
    if (gamma[0] == 0.0f) return;

    const int t = threadIdx.x;
    __shared__ float red[8];
    __shared__ float s_max, s_sum;

    for (int row = blockIdx.x; row < BB * CC; row += gridDim.x) {
        float* p = g_aTa + (size_t)row * CC;
        const float v = p[t];

        // max reduce
        float m = v;
        #pragma unroll
        for (int o = 16; o; o >>= 1) m = fmaxf(m, __shfl_xor_sync(0xffffffffu, m, o));
        if ((t & 31) == 0) red[t >> 5] = m;
        __syncthreads();
        if (t == 0) {
            float mm = red[0];
            #pragma unroll
            for (int i = 1; i < 8; i++) mm = fmaxf(mm, red[i]);
            s_max = mm;
        }
        __syncthreads();

        const float e = expf(v - s_max);

        // sum reduce
        float s = e;
        #pragma unroll
        for (int o = 16; o; o >>= 1) s += __shfl_xor_sync(0xffffffffu, s, o);
        if ((t & 31) == 0) red[t >> 5] = s;
        __syncthreads();
        if (t == 0) {
            float ss = red[0];
            #pragma unroll
            for (int i = 1; i < 8; i++) ss += red[i];
            s_sum = ss;
        }
        __syncthreads();

        p[t] = e / s_sum;
        __syncthreads();   // protect red[] / s_max reuse across row iterations
    }
}

// ---------------------------------------------------------------------------
// Kernel 3: out = gamma * (x @ attn) + x   (fused epilogue)
// gamma==0 fast path: vectorized float4 copy out = x (bit-exact).
// ---------------------------------------------------------------------------
__global__ void k_out(const float* __restrict__ x, const float* __restrict__ gamma,
                      float* __restrict__ out) {
    const float g = gamma[0];

    if (g == 0.0f) {
        const float4* __restrict__ xin = (const float4*)x;
        float4* __restrict__ o = (float4*)out;
        const size_t total = (size_t)BB * NN * CC / 4;   // 8.4M float4
        for (size_t i = (size_t)blockIdx.x * blockDim.x + threadIdx.x; i < total;
             i += (size_t)gridDim.x * blockDim.x)
            o[i] = xin[i];
        return;
    }

    // General path: aaTa[b,n,d] = sum_c x[b,n,c] * attn[b,c,d]
    // Tiles: 64(n) x 64(d), K=256 in chunks of 32. Grid-stride over tiles.
    __shared__ float As[64][33];   // [n][k-chunk]
    __shared__ float Bs[32][68];   // [k-chunk][d]

    const int tilesN = NN / 64;            // 64
    const int tilesD = CC / 64;            // 4
    const int tilesPerB = tilesN * tilesD; // 256
    const int nTiles = BB * tilesPerB;     // 8192

    const int tc = threadIdx.x & 15;
    const int tr = threadIdx.x >> 4;

    for (int tile = blockIdx.x; tile < nTiles; tile += gridDim.x) {
        const int b  = tile / tilesPerB;
        const int r  = tile % tilesPerB;
        const int n0 = (r / tilesD) * 64;
        const int d0 = (r % tilesD) * 64;

        const float* xb   = x + (size_t)b * NN * CC;
        const float* attn = g_aTa + (size_t)b * CC * CC;

        float acc[4][4] = {};

        for (int k0 = 0; k0 < CC; k0 += 32) {
            for (int i = threadIdx.x; i < 64 * 32; i += 256) {
                const int nn = i >> 5, kk = i & 31;
                As[nn][kk] = xb[(size_t)(n0 + nn) * CC + k0 + kk];
            }
            for (int i = threadIdx.x; i < 32 * 64; i += 256) {
                const int kk = i >> 6, dd = i & 63;
                Bs[kk][dd] = attn[(size_t)(k0 + kk) * CC + d0 + dd];
            }
            __syncthreads();
            #pragma unroll
            for (int kk = 0; kk < 32; kk++) {
                float a[4], bb[4];
                #pragma unroll
                for (int i = 0; i < 4; i++) a[i]  = As[tr * 4 + i][kk];
                #pragma unroll
                for (int j = 0; j < 4; j++) bb[j] = Bs[kk][tc * 4 + j];
                #pragma unroll
                for (int i = 0; i < 4; i++)
                    #pragma unroll
                    for (int j = 0; j < 4; j++)
                        acc[i][j] = fmaf(a[i], bb[j], acc[i][j]);
            }
            __syncthreads();
        }

        #pragma unroll
        for (int i = 0; i < 4; i++) {
            const size_t row = (size_t)b * NN + n0 + tr * 4 + i;
            #pragma unroll
            for (int j = 0; j < 4; j++) {
                const size_t idx = row * CC + d0 + tc * 4 + j;
                out[idx] = fmaf(g, acc[i][j], x[idx]);
            }
        }
        __syncthreads();
    }
}

// ---------------------------------------------------------------------------
extern "C" void kernel_launch(void* const* d_in, const int* in_sizes, int n_in,
                              void* d_out, int out_size) {
    const float* x     = (const float*)d_in[0];
    const float* gamma = (const float*)d_in[1];
    float* out         = (float*)d_out;

    dim3 g1(CC / 64, CC / 64, BB);           // 4 x 4 x 32 = 512 blocks
    k_aTa<<<g1, 256>>>(x, gamma);
    k_softmax<<<448, 256>>>(gamma);          // persistent rows; cheap early-exit
    k_out<<<1184, 256>>>(x, gamma, out);     // 148 SMs x 8 blocks: one full wave
}

// round 5
// speedup vs baseline: 1.0372x; 1.0372x over previous
#include <cuda_runtime.h>
#include <cstdint>

// Problem dims (fixed by the dataset)
#define BB 32
#define NN 4096          // 64*64
#define CC 256

// 8 MB scratch for aTa / attn (in-place softmax). __device__ global: allowed.
__device__ float g_aTa[(size_t)BB * CC * CC];

// ---------------------------------------------------------------------------
// Kernel 1: aTa[b,c,d] = sum_n x[b,n,c] * x[b,n,d]
// Persistent grid: 148 blocks stride over 512 (4x4x32) tiles.
// 64x64 tile, 4x4 micro-tile, K-chunk 32, 256 threads.
// ---------------------------------------------------------------------------
__global__ void k_aTa(const float* __restrict__ x, const float* __restrict__ gamma) {
    if (gamma[0] == 0.0f) return;   // gamma==0 => gamma*aaTa == 0, skip all work

    __shared__ float As[32][68];    // [n-chunk][c]   (+4 pad vs bank conflicts)
    __shared__ float Bs[32][68];    // [n-chunk][d]

    const int tc = threadIdx.x & 15;   // 16 col-groups of 4
    const int tr = threadIdx.x >> 4;   // 16 row-groups of 4
    const int nTiles = BB * 4 * 4;     // 512

    for (int tile = blockIdx.x; tile < nTiles; tile += gridDim.x) {
        const int b  = tile >> 4;
        const int c0 = ((tile >> 2) & 3) * 64;
        const int d0 = (tile & 3) * 64;

        const float* xb = x + (size_t)b * NN * CC;
        float acc[4][4] = {};

        for (int n0 = 0; n0 < NN; n0 += 32) {
            for (int i = threadIdx.x; i < 32 * 64; i += 256) {
                const int nn = i >> 6, cc = i & 63;
                const size_t base = (size_t)(n0 + nn) * CC;
                As[nn][cc] = xb[base + c0 + cc];
                Bs[nn][cc] = xb[base + d0 + cc];
            }
            __syncthreads();
            #pragma unroll
            for (int kk = 0; kk < 32; kk++) {
                float a[4], bb[4];
                #pragma unroll
                for (int i = 0; i < 4; i++) a[i]  = As[kk][tr * 4 + i];
                #pragma unroll
                for (int j = 0; j < 4; j++) bb[j] = Bs[kk][tc * 4 + j];
                #pragma unroll
                for (int i = 0; i < 4; i++)
                    #pragma unroll
                    for (int j = 0; j < 4; j++)
                        acc[i][j] = fmaf(a[i], bb[j], acc[i][j]);
            }
            __syncthreads();
        }

        float* outp = g_aTa + (size_t)b * CC * CC;
        #pragma unroll
        for (int i = 0; i < 4; i++)
            #pragma unroll
            for (int j = 0; j < 4; j++)
                outp[(size_t)(c0 + tr * 4 + i) * CC + d0 + tc * 4 + j] = acc[i][j];
        __syncthreads();
    }
}

// ---------------------------------------------------------------------------
// Kernel 2: row-wise stable softmax over last axis of aTa, in place.
// Persistent grid: 148 blocks loop over all BB*CC rows (cheap early-exit).
// ---------------------------------------------------------------------------
__global__ void k_softmax(const float* __restrict__ gamma) {
    if (gamma[0] == 0.0f) return;

    const int t = threadIdx.x;
    __shared__ float red[8];
    __shared__ float s_max, s_sum;

    for (int row = blockIdx.x; row < BB * CC; row += gridDim.x) {
        float* p = g_aTa + (size_t)row * CC;
        const float v = p[t];

        // max reduce
        float m = v;
        #pragma unroll
        for (int o = 16; o; o >>= 1) m = fmaxf(m, __shfl_xor_sync(0xffffffffu, m, o));
        if ((t & 31) == 0) red[t >> 5] = m;
        __syncthreads();
        if (t == 0) {
            float mm = red[0];
            #pragma unroll
            for (int i = 1; i < 8; i++) mm = fmaxf(mm, red[i]);
            s_max = mm;
        }
        __syncthreads();

        const float e = expf(v - s_max);

        // sum reduce
        float s = e;
        #pragma unroll
        for (int o = 16; o; o >>= 1) s += __shfl_xor_sync(0xffffffffu, s, o);
        if ((t & 31) == 0) red[t >> 5] = s;
        __syncthreads();
        if (t == 0) {
            float ss = red[0];
            #pragma unroll
            for (int i = 1; i < 8; i++) ss += red[i];
            s_sum = ss;
        }
        __syncthreads();

        p[t] = e / s_sum;
        __syncthreads();   // protect red[] / s_max reuse across row iterations
    }
}

// ---------------------------------------------------------------------------
// Kernel 3 (general path only): out = gamma * (x @ attn) + x
// gamma==0: early-exit — the memcpy node already produced out = x.
// ---------------------------------------------------------------------------
__global__ void k_out(const float* __restrict__ x, const float* __restrict__ gamma,
                      float* __restrict__ out) {
    const float g = gamma[0];
    if (g == 0.0f) return;

    // aaTa[b,n,d] = sum_c x[b,n,c] * attn[b,c,d]
    // Tiles: 64(n) x 64(d), K=256 in chunks of 32. Grid-stride over tiles.
    __shared__ float As[64][33];   // [n][k-chunk]
    __shared__ float Bs[32][68];   // [k-chunk][d]

    const int tilesD = CC / 64;                 // 4
    const int tilesPerB = (NN / 64) * tilesD;   // 256
    const int nTiles = BB * tilesPerB;          // 8192

    const int tc = threadIdx.x & 15;
    const int tr = threadIdx.x >> 4;

    for (int tile = blockIdx.x; tile < nTiles; tile += gridDim.x) {
        const int b  = tile / tilesPerB;
        const int r  = tile % tilesPerB;
        const int n0 = (r / tilesD) * 64;
        const int d0 = (r % tilesD) * 64;

        const float* xb   = x + (size_t)b * NN * CC;
        const float* attn = g_aTa + (size_t)b * CC * CC;

        float acc[4][4] = {};

        for (int k0 = 0; k0 < CC; k0 += 32) {
            for (int i = threadIdx.x; i < 64 * 32; i += 256) {
                const int nn = i >> 5, kk = i & 31;
                As[nn][kk] = xb[(size_t)(n0 + nn) * CC + k0 + kk];
            }
            for (int i = threadIdx.x; i < 32 * 64; i += 256) {
                const int kk = i >> 6, dd = i & 63;
                Bs[kk][dd] = attn[(size_t)(k0 + kk) * CC + d0 + dd];
            }
            __syncthreads();
            #pragma unroll
            for (int kk = 0; kk < 32; kk++) {
                float a[4], bb[4];
                #pragma unroll
                for (int i = 0; i < 4; i++) a[i]  = As[tr * 4 + i][kk];
                #pragma unroll
                for (int j = 0; j < 4; j++) bb[j] = Bs[kk][tc * 4 + j];
                #pragma unroll
                for (int i = 0; i < 4; i++)
                    #pragma unroll
                    for (int j = 0; j < 4; j++)
                        acc[i][j] = fmaf(a[i], bb[j], acc[i][j]);
            }
            __syncthreads();
        }

        #pragma unroll
        for (int i = 0; i < 4; i++) {
            const size_t row = (size_t)b * NN + n0 + tr * 4 + i;
            #pragma unroll
            for (int j = 0; j < 4; j++) {
                const size_t idx = row * CC + d0 + tc * 4 + j;
                out[idx] = fmaf(g, acc[i][j], x[idx]);
            }
        }
        __syncthreads();
    }
}

// ---------------------------------------------------------------------------
extern "C" void kernel_launch(void* const* d_in, const int* in_sizes, int n_in,
                              void* d_out, int out_size) {
    const float* x     = (const float*)d_in[0];
    const float* gamma = (const float*)d_in[1];
    float* out         = (float*)d_out;

    // Unconditional D2D copy: out = x. Correct for gamma==0 (final answer) and
    // gamma!=0 (k_out overwrites every element afterwards, stream-ordered).
    cudaMemcpyAsync(out, x, (size_t)BB * NN * CC * sizeof(float),
                    cudaMemcpyDeviceToDevice, 0);

    k_aTa<<<148, 256>>>(x, gamma);       // persistent tiles; cheap early-exit
    k_softmax<<<148, 256>>>(gamma);      // persistent rows; cheap early-exit
    k_out<<<592, 256>>>(x, gamma, out);  // general path only; early-exit on 0
}